// round 4
// baseline (speedup 1.0000x reference)
#include <cuda_runtime.h>

// FastWaveNet autoregressive sampler.
// T=512 sequential steps; single persistent CTA does the recurrence,
// two tiny prep kernels zero the history ring and precompute per-frame conds.

#define TT   512
#define LL   10
#define RR   64
#define GG   128
#define SSZ  256
#define NCLS 256

// scratch (device globals; no allocation allowed)
__device__ float d_hist[TT * LL * RR];   // [slot][j][r]
__device__ float d_conds[8 * LL * GG];   // [frame][j*128+g]

__global__ void k_zero_hist() {
    int i = blockIdx.x * blockDim.x + threadIdx.x;
    if (i < TT * LL * RR) d_hist[i] = 0.f;
}

// conds[f][row] = sum_m condition_W[row, m] * y[m, f],  row = j*128+g
__global__ void k_conds(const float* __restrict__ condW, const float* __restrict__ y) {
    int i = blockIdx.x * blockDim.x + threadIdx.x;
    if (i >= 1280 * 8) return;
    int row = i >> 3, f = i & 7;
    const float* w = condW + row * 80;
    float a = 0.f;
#pragma unroll
    for (int m = 0; m < 80; ++m) a += w[m] * y[m * 8 + f];
    d_conds[f * 1280 + row] = a;
}

__device__ __forceinline__ float dot4(float4 a, float4 b) {
    return a.x * b.x + a.y * b.y + a.z * b.z + a.w * b.w;
}

__global__ void __launch_bounds__(1024, 1) k_main(
    const float* __restrict__ emb,
    const float* __restrict__ wpast,
    const float* __restrict__ wpres,
    const float* __restrict__ wo,  const float* __restrict__ wob,
    const float* __restrict__ wol, const float* __restrict__ wobl,
    const float* __restrict__ e1w, const float* __restrict__ e1b,
    const float* __restrict__ e2w, const float* __restrict__ e2b,
    const float* __restrict__ samples,
    float* __restrict__ out)     // output compared as float32 per metadata
{
    __shared__ __align__(16) float xa[64], xb[64], hsm[128], zsm[64];
    __shared__ __align__(16) float skip[256], rsm[256], hid[256], buf[256], cs[256];
    __shared__ __align__(16) float pasts[LL][RR];
    __shared__ float wred[32], scn[32], shv[2];
    __shared__ unsigned ibal[8];
    __shared__ int s_new;

    const int tid  = threadIdx.x;
    const int lane = tid & 31;
    const int wid  = tid >> 5;
    int prev = NCLS / 2 - 1;   // 127

    for (int t = 0; t < TT; ++t) {
        const int frame = t >> 6;

        // --- step prologue: past vectors, x0 = emb[prev], skip = 0 ---
        if (tid < 640) {
            int j = tid >> 6, r = tid & 63;
            int slot = (t + 512 - (1 << j)) & 511;
            pasts[j][r] = d_hist[slot * 640 + j * 64 + r];
        }
        if (tid < 64)  xa[tid]   = emb[prev * 64 + tid];
        if (tid < 256) skip[tid] = 0.f;
        __syncthreads();

#pragma unroll 1
        for (int j = 0; j < LL; ++j) {
            float* xin  = (j & 1) ? xb : xa;
            float* xout = (j & 1) ? xa : xb;

            // phase 1: h[g] = cond + Wpast[j]@past + Wpres[j]@x   (8 threads/row)
            {
                int g = tid >> 3, sub = tid & 7;
                const float* wp = wpast + ((j * GG + g) * RR + sub * 8);
                const float* wq = wpres + ((j * GG + g) * RR + sub * 8);
                float cond = 0.f;
                if (sub == 0) cond = d_conds[frame * 1280 + j * GG + g];
                float4 a0 = *(const float4*)(wp);
                float4 a1 = *(const float4*)(wp + 4);
                float4 b0 = *(const float4*)(wq);
                float4 b1 = *(const float4*)(wq + 4);
                float4 p0 = *(const float4*)&pasts[j][sub * 8];
                float4 p1 = *(const float4*)&pasts[j][sub * 8 + 4];
                float4 x0 = *(const float4*)&xin[sub * 8];
                float4 x1 = *(const float4*)&xin[sub * 8 + 4];
                float acc = (dot4(a0, p0) + dot4(a1, p1)) + (dot4(b0, x0) + dot4(b1, x1));
                acc += __shfl_xor_sync(~0u, acc, 1);
                acc += __shfl_xor_sync(~0u, acc, 2);
                acc += __shfl_xor_sync(~0u, acc, 4);
                if (sub == 0) hsm[g] = acc + cond;
                // written[j] = layer input x (pre-update); pasts were read at step start
                if (sub == 7 && g < 64) d_hist[(t & 511) * 640 + j * 64 + g] = xin[g];
            }
            __syncthreads();

            if (tid < 64) {
                float zw = hsm[tid], zf = hsm[tid + 64];
                zsm[tid] = tanhf(zw) * (1.f / (1.f + expf(-zf)));
            }
            __syncthreads();

            if (j < LL - 1) {
                // o[320] = W_o[j]@z + b ; x += o[:64] ; skip += o[64:]   (2 threads/row)
                if (tid < 640) {
                    int m = tid >> 1, half = tid & 1;
                    const float* w = wo + ((j * 320 + m) * 64 + half * 32);
                    float av = 0.f, bv = 0.f;
#pragma unroll
                    for (int k = 0; k < 8; k += 2) {
                        float4 w0 = *(const float4*)(w + k * 4);
                        float4 w1 = *(const float4*)(w + k * 4 + 4);
                        float4 z0 = *(const float4*)&zsm[half * 32 + k * 4];
                        float4 z1 = *(const float4*)&zsm[half * 32 + k * 4 + 4];
                        av += dot4(w0, z0);
                        bv += dot4(w1, z1);
                    }
                    float acc2 = av + bv;
                    acc2 += __shfl_xor_sync(~0u, acc2, 1);
                    if (half == 0) {
                        float o = acc2 + wob[j * 320 + m];
                        if (m < 64) xout[m] = xin[m] + o;
                        else        skip[m - 64] += o;
                    }
                }
            } else {
                // last layer: skip += W_o_last@z + b_last   (4 threads/row)
                int m = tid >> 2, q = tid & 3;
                const float* w = wol + m * 64 + q * 16;
                float av = 0.f, bv = 0.f;
#pragma unroll
                for (int k = 0; k < 4; k += 2) {
                    float4 w0 = *(const float4*)(w + k * 4);
                    float4 w1 = *(const float4*)(w + k * 4 + 4);
                    float4 z0 = *(const float4*)&zsm[q * 16 + k * 4];
                    float4 z1 = *(const float4*)&zsm[q * 16 + k * 4 + 4];
                    av += dot4(w0, z0);
                    bv += dot4(w1, z1);
                }
                float acc2 = av + bv;
                acc2 += __shfl_xor_sync(~0u, acc2, 1);
                acc2 += __shfl_xor_sync(~0u, acc2, 2);
                if (q == 0) skip[m] += acc2 + wobl[m];
            }
            __syncthreads();
        }

        // --- head: hid = relu(e1w @ relu(skip) + e1b); logits = e2w @ hid + e2b ---
        if (tid < 256) rsm[tid] = fmaxf(skip[tid], 0.f);
        __syncthreads();
        {
            int e = tid >> 2, q = tid & 3;
            const float* w = e1w + e * 256 + q * 64;
            float av = 0.f, bv = 0.f, cv = 0.f, dv = 0.f;
#pragma unroll
            for (int k = 0; k < 16; k += 4) {
                float4 w0 = *(const float4*)(w + k * 4);
                float4 w1 = *(const float4*)(w + k * 4 + 4);
                float4 w2 = *(const float4*)(w + k * 4 + 8);
                float4 w3 = *(const float4*)(w + k * 4 + 12);
                float4 r0 = *(const float4*)&rsm[q * 64 + k * 4];
                float4 r1 = *(const float4*)&rsm[q * 64 + k * 4 + 4];
                float4 r2 = *(const float4*)&rsm[q * 64 + k * 4 + 8];
                float4 r3 = *(const float4*)&rsm[q * 64 + k * 4 + 12];
                av += dot4(w0, r0); bv += dot4(w1, r1);
                cv += dot4(w2, r2); dv += dot4(w3, r3);
            }
            float acc = (av + bv) + (cv + dv);
            acc += __shfl_xor_sync(~0u, acc, 1);
            acc += __shfl_xor_sync(~0u, acc, 2);
            if (q == 0) hid[e] = fmaxf(acc + e1b[e], 0.f);
        }
        __syncthreads();
        {
            int n = tid >> 2, q = tid & 3;
            const float* w = e2w + n * 256 + q * 64;
            float av = 0.f, bv = 0.f, cv = 0.f, dv = 0.f;
#pragma unroll
            for (int k = 0; k < 16; k += 4) {
                float4 w0 = *(const float4*)(w + k * 4);
                float4 w1 = *(const float4*)(w + k * 4 + 4);
                float4 w2 = *(const float4*)(w + k * 4 + 8);
                float4 w3 = *(const float4*)(w + k * 4 + 12);
                float4 r0 = *(const float4*)&hid[q * 64 + k * 4];
                float4 r1 = *(const float4*)&hid[q * 64 + k * 4 + 4];
                float4 r2 = *(const float4*)&hid[q * 64 + k * 4 + 8];
                float4 r3 = *(const float4*)&hid[q * 64 + k * 4 + 12];
                av += dot4(w0, r0); bv += dot4(w1, r1);
                cv += dot4(w2, r2); dv += dot4(w3, r3);
            }
            float acc = (av + bv) + (cv + dv);
            acc += __shfl_xor_sync(~0u, acc, 1);
            acc += __shfl_xor_sync(~0u, acc, 2);
            if (q == 0) buf[n] = acc + e2b[n];   // logits (c == 1)
        }
        __syncthreads();

        // --- softmax -> cumsum -> first index with cumsum > s ---
        float l = (tid < 256) ? buf[tid] : -1e30f;
        {
            float v = l;
#pragma unroll
            for (int o = 16; o; o >>= 1) v = fmaxf(v, __shfl_xor_sync(~0u, v, o));
            if (lane == 0) wred[wid] = v;
        }
        __syncthreads();
        if (tid < 32) {
            float m2 = wred[tid];
#pragma unroll
            for (int o = 16; o; o >>= 1) m2 = fmaxf(m2, __shfl_xor_sync(~0u, m2, o));
            if (tid == 0) shv[0] = m2;
        }
        __syncthreads();
        float mx = shv[0];
        float ev = (tid < 256) ? expf(l - mx) : 0.f;
        if (tid < 256) buf[tid] = ev;
        {
            float v = ev;
#pragma unroll
            for (int o = 16; o; o >>= 1) v += __shfl_xor_sync(~0u, v, o);
            if (lane == 0) wred[wid] = v;
        }
        __syncthreads();
        if (tid < 32) {
            float s2 = wred[tid];
#pragma unroll
            for (int o = 16; o; o >>= 1) s2 += __shfl_xor_sync(~0u, s2, o);
            if (tid == 0) shv[1] = s2;
        }
        __syncthreads();
        float Z = shv[1];
        if (tid < 256) buf[tid] = buf[tid] / Z;   // p_i
        __syncthreads();
        if (tid < 32) {
            float ssum = 0.f;
#pragma unroll
            for (int k = 0; k < 8; ++k) ssum += buf[tid * 8 + k];
#pragma unroll
            for (int d = 1; d < 32; d <<= 1) {
                float u = __shfl_up_sync(~0u, ssum, d);
                if (lane >= d) ssum += u;
            }
            scn[tid] = ssum;   // inclusive 8-block sums
        }
        __syncthreads();
        if (tid < 256) {
            int b = tid >> 3;
            float c0 = b ? scn[b - 1] : 0.f;
            for (int k = b * 8; k <= tid; ++k) c0 += buf[k];
            cs[tid] = c0;      // inclusive cumsum of p
        }
        __syncthreads();
        {
            float sv = samples[t];
            bool pred = (tid < 256) && (cs[tid] > sv);
            unsigned bal = __ballot_sync(~0u, pred);
            if (lane == 0 && wid < 8) ibal[wid] = bal;
        }
        __syncthreads();
        if (tid == 0) {
            int nw = 0; bool found = false;
#pragma unroll
            for (int w2 = 0; w2 < 8; ++w2) {
                if (!found && ibal[w2]) { nw = w2 * 32 + __ffs(ibal[w2]) - 1; found = true; }
            }
            s_new = found ? nw : 0;   // argmax over all-False booleans -> 0
            out[t] = (float)s_new;    // write as float32 (output dtype per metadata)
        }
        __syncthreads();
        prev = s_new;
    }
}

extern "C" void kernel_launch(void* const* d_in, const int* in_sizes, int n_in,
                              void* d_out, int out_size) {
    // Robust size-verified mapping (dict order of setup_inputs, skipping any
    // entries -- e.g. the scalar c -- whose size doesn't match the next
    // expected array size). Expected element counts:
    //   y=640, samples=512, emb=16384, condW=102400, wpast=81920, wpres=81920,
    //   wo=184320, wob=2880, wol=16384, wobl=256, e1w=65536, e1b=256,
    //   e2w=65536, e2b=256
    const int want[14] = {640, 512, 16384, 102400, 81920, 81920, 184320,
                          2880, 16384, 256, 65536, 256, 65536, 256};
    const float* ptr[14];
    int j = 0;
    for (int i = 0; i < 14; ++i) {
        while (j < n_in && in_sizes[j] != want[i]) ++j;
        ptr[i] = (j < n_in) ? (const float*)d_in[j] : (const float*)d_in[n_in - 1];
        ++j;
    }
    const float* y       = ptr[0];
    const float* samples = ptr[1];
    const float* emb     = ptr[2];
    const float* condW   = ptr[3];
    const float* wpast   = ptr[4];
    const float* wpres   = ptr[5];
    const float* wo      = ptr[6];
    const float* wob     = ptr[7];
    const float* wol     = ptr[8];
    const float* wobl    = ptr[9];
    const float* e1w     = ptr[10];
    const float* e1b     = ptr[11];
    const float* e2w     = ptr[12];
    const float* e2b     = ptr[13];
    float* out = (float*)d_out;

    k_zero_hist<<<(TT * LL * RR + 1023) / 1024, 1024>>>();
    k_conds<<<(1280 * 8 + 255) / 256, 256>>>(condW, y);
    k_main<<<1, 1024>>>(emb, wpast, wpres, wo, wob, wol, wobl,
                        e1w, e1b, e2w, e2b, samples, out);
}

// round 5
// speedup vs baseline: 2.3641x; 2.3641x over previous
#include <cuda_runtime.h>

// FastWaveNet autoregressive sampler — coalesced matvec edition.
// T=512 sequential steps; single persistent CTA; all matvecs re-mapped so
// warp lanes read contiguous K-chunks (nL=4 per LDG.128 instead of 32).

#define TT   512
#define LL   10
#define RR   64
#define GG   128
#define SSZ  256
#define NCLS 256

__device__ float d_hist[TT * LL * RR];   // [slot][j][r]
__device__ float d_conds[8 * LL * GG];   // [frame][j*128+g]

__global__ void k_zero_hist() {
    int i = blockIdx.x * blockDim.x + threadIdx.x;
    if (i < TT * LL * RR) d_hist[i] = 0.f;
}

__global__ void k_conds(const float* __restrict__ condW, const float* __restrict__ y) {
    int i = blockIdx.x * blockDim.x + threadIdx.x;
    if (i >= 1280 * 8) return;
    int row = i >> 3, f = i & 7;
    const float* w = condW + row * 80;
    float a = 0.f;
#pragma unroll
    for (int m = 0; m < 80; ++m) a += w[m] * y[m * 8 + f];
    d_conds[f * 1280 + row] = a;
}

__device__ __forceinline__ float dot4(float4 a, float4 b) {
    return a.x * b.x + a.y * b.y + a.z * b.z + a.w * b.w;
}
__device__ __forceinline__ float red16(float v) {   // sum within 16-lane groups
    v += __shfl_xor_sync(~0u, v, 1);
    v += __shfl_xor_sync(~0u, v, 2);
    v += __shfl_xor_sync(~0u, v, 4);
    v += __shfl_xor_sync(~0u, v, 8);
    return v;
}
__device__ __forceinline__ float red32(float v) {   // full-warp sum
    v += __shfl_xor_sync(~0u, v, 1);
    v += __shfl_xor_sync(~0u, v, 2);
    v += __shfl_xor_sync(~0u, v, 4);
    v += __shfl_xor_sync(~0u, v, 8);
    v += __shfl_xor_sync(~0u, v, 16);
    return v;
}

__global__ void __launch_bounds__(1024, 1) k_main(
    const float* __restrict__ emb,
    const float* __restrict__ wpast,
    const float* __restrict__ wpres,
    const float* __restrict__ wo,  const float* __restrict__ wob,
    const float* __restrict__ wol, const float* __restrict__ wobl,
    const float* __restrict__ e1w, const float* __restrict__ e1b,
    const float* __restrict__ e2w, const float* __restrict__ e2b,
    const float* __restrict__ samples,
    float* __restrict__ out)     // output dtype: float32
{
    __shared__ __align__(16) float xa[64], xb[64], zsm[64];
    __shared__ __align__(16) float hsm_a[128], hsm_b[128];
    __shared__ __align__(16) float skip[256], rsm[256], hid[256], buf[256], cs[256];
    __shared__ __align__(16) float pasts[LL][RR];
    __shared__ float wred[32], scn[32], shv[2];
    __shared__ unsigned ibal[8];
    __shared__ int s_new;

    const int tid  = threadIdx.x;
    const int lane = tid & 31;
    const int wid  = tid >> 5;
    const int sub  = lane & 15;   // float4 index within a 64-wide row
    const int half = lane >> 4;   // which of the 2 rows this warp-LDG covers
    int prev = NCLS / 2 - 1;      // 127

    for (int t = 0; t < TT; ++t) {
        const int frame = t >> 6;

        // --- step prologue ---
        if (tid < 640) {
            int j = tid >> 6, r = tid & 63;
            int slot = (t + 512 - (1 << j)) & 511;
            pasts[j][r] = d_hist[slot * 640 + j * 64 + r];
        }
        if (tid < 64)  xa[tid]   = emb[prev * 64 + tid];
        if (tid < 256) skip[tid] = 0.f;
        __syncthreads();

#pragma unroll 1
        for (int j = 0; j < LL; ++j) {
            float* xin  = (j & 1) ? xb : xa;
            float* xout = (j & 1) ? xa : xb;

            // ---- phase 1: 256 row-dots of length 64 (wpast rows then wpres rows)
            // warp w<16: wpast rows 8w..8w+7 ; warp w>=16: wpres rows 8(w-16)..
            {
                const bool  isB   = (wid >= 16);
                const int   wbase = isB ? (wid - 16) : wid;
                const float* W    = (isB ? wpres : wpast) + j * (GG * RR);
                const float* V    = isB ? xin : pasts[j];
                float4 wv[4];
#pragma unroll
                for (int p = 0; p < 4; ++p) {
                    int g = wbase * 8 + p * 2 + half;
                    wv[p] = *(const float4*)(W + g * 64 + sub * 4);
                }
                float4 vv = *(const float4*)(V + sub * 4);
                float* dst = isB ? hsm_b : hsm_a;
#pragma unroll
                for (int p = 0; p < 4; ++p) {
                    float acc = red16(dot4(wv[p], vv));
                    if (sub == 0) dst[wbase * 8 + p * 2 + half] = acc;
                }
            }
            __syncthreads();

            // ---- activation + history write (threads 0..63)
            if (tid < 64) {
                const float* cbase = d_conds + frame * 1280 + j * GG;
                float zw = hsm_a[tid]      + hsm_b[tid]      + cbase[tid];
                float zf = hsm_a[tid + 64] + hsm_b[tid + 64] + cbase[tid + 64];
                zsm[tid] = tanhf(zw) * (1.f / (1.f + expf(-zf)));
                // written[j] = layer input x (pre-update)
                d_hist[(t & 511) * 640 + j * 64 + tid] = xin[tid];
            }
            __syncthreads();

            // ---- phase 3: W_o matvec, coalesced 2-rows-per-warp-LDG
            if (j < LL - 1) {
                // 320 rows: warp w handles pairs w*5+p, p=0..4
                const float* W = wo + j * (320 * 64);
                float4 wv[5];
#pragma unroll
                for (int p = 0; p < 5; ++p) {
                    int r = (wid * 5 + p) * 2 + half;
                    wv[p] = *(const float4*)(W + r * 64 + sub * 4);
                }
                float4 vv = *(const float4*)(zsm + sub * 4);
#pragma unroll
                for (int p = 0; p < 5; ++p) {
                    float acc = red16(dot4(wv[p], vv));
                    if (sub == 0) {
                        int r = (wid * 5 + p) * 2 + half;
                        float o = acc + wob[j * 320 + r];
                        if (r < 64) xout[r] = xin[r] + o;
                        else        skip[r - 64] += o;
                    }
                }
            } else {
                // last layer: 256 rows of wol; warp w handles pairs w*4+p, p=0..3
                float4 wv[4];
#pragma unroll
                for (int p = 0; p < 4; ++p) {
                    int r = (wid * 4 + p) * 2 + half;
                    wv[p] = *(const float4*)(wol + r * 64 + sub * 4);
                }
                float4 vv = *(const float4*)(zsm + sub * 4);
#pragma unroll
                for (int p = 0; p < 4; ++p) {
                    float acc = red16(dot4(wv[p], vv));
                    if (sub == 0) {
                        int r = (wid * 4 + p) * 2 + half;
                        skip[r] += acc + wobl[r];
                    }
                }
            }
            __syncthreads();
        }

        // --- head ---
        if (tid < 256) rsm[tid] = fmaxf(skip[tid], 0.f);
        __syncthreads();

        // e1: 256 rows x 256; one warp per row, 8 rows/warp, 2 batches of 4
        {
            float4 v0 = *(const float4*)(rsm + lane * 4);
            float4 v1 = *(const float4*)(rsm + 128 + lane * 4);
#pragma unroll
            for (int batch = 0; batch < 2; ++batch) {
                int r0 = wid * 8 + batch * 4;
                float4 a0[4], a1[4];
#pragma unroll
                for (int i = 0; i < 4; ++i) {
                    const float* wr = e1w + (r0 + i) * 256;
                    a0[i] = *(const float4*)(wr + lane * 4);
                    a1[i] = *(const float4*)(wr + 128 + lane * 4);
                }
#pragma unroll
                for (int i = 0; i < 4; ++i) {
                    float acc = red32(dot4(a0[i], v0) + dot4(a1[i], v1));
                    if (lane == 0) hid[r0 + i] = fmaxf(acc + e1b[r0 + i], 0.f);
                }
            }
        }
        __syncthreads();

        // e2: logits
        {
            float4 v0 = *(const float4*)(hid + lane * 4);
            float4 v1 = *(const float4*)(hid + 128 + lane * 4);
#pragma unroll
            for (int batch = 0; batch < 2; ++batch) {
                int r0 = wid * 8 + batch * 4;
                float4 a0[4], a1[4];
#pragma unroll
                for (int i = 0; i < 4; ++i) {
                    const float* wr = e2w + (r0 + i) * 256;
                    a0[i] = *(const float4*)(wr + lane * 4);
                    a1[i] = *(const float4*)(wr + 128 + lane * 4);
                }
#pragma unroll
                for (int i = 0; i < 4; ++i) {
                    float acc = red32(dot4(a0[i], v0) + dot4(a1[i], v1));
                    if (lane == 0) buf[r0 + i] = acc + e2b[r0 + i];  // logits (c==1)
                }
            }
        }
        __syncthreads();

        // --- softmax -> cumsum -> first index with cumsum > s ---
        float l = (tid < 256) ? buf[tid] : -1e30f;
        {
            float v = l;
#pragma unroll
            for (int o = 16; o; o >>= 1) v = fmaxf(v, __shfl_xor_sync(~0u, v, o));
            if (lane == 0) wred[wid] = v;
        }
        __syncthreads();
        if (tid < 32) {
            float m2 = wred[tid];
#pragma unroll
            for (int o = 16; o; o >>= 1) m2 = fmaxf(m2, __shfl_xor_sync(~0u, m2, o));
            if (tid == 0) shv[0] = m2;
        }
        __syncthreads();
        float mx = shv[0];
        float ev = (tid < 256) ? expf(l - mx) : 0.f;
        if (tid < 256) buf[tid] = ev;
        {
            float v = ev;
#pragma unroll
            for (int o = 16; o; o >>= 1) v += __shfl_xor_sync(~0u, v, o);
            if (lane == 0) wred[wid] = v;
        }
        __syncthreads();
        if (tid < 32) {
            float s2 = wred[tid];
#pragma unroll
            for (int o = 16; o; o >>= 1) s2 += __shfl_xor_sync(~0u, s2, o);
            if (tid == 0) shv[1] = s2;
        }
        __syncthreads();
        float Z = shv[1];
        if (tid < 256) buf[tid] = buf[tid] / Z;   // p_i
        __syncthreads();
        if (tid < 32) {
            float ssum = 0.f;
#pragma unroll
            for (int k = 0; k < 8; ++k) ssum += buf[tid * 8 + k];
#pragma unroll
            for (int d = 1; d < 32; d <<= 1) {
                float u = __shfl_up_sync(~0u, ssum, d);
                if (lane >= d) ssum += u;
            }
            scn[tid] = ssum;   // inclusive 8-block sums
        }
        __syncthreads();
        if (tid < 256) {
            int b = tid >> 3;
            float c0 = b ? scn[b - 1] : 0.f;
            for (int k = b * 8; k <= tid; ++k) c0 += buf[k];
            cs[tid] = c0;      // inclusive cumsum of p
        }
        __syncthreads();
        {
            float sv = samples[t];
            bool pred = (tid < 256) && (cs[tid] > sv);
            unsigned bal = __ballot_sync(~0u, pred);
            if (lane == 0 && wid < 8) ibal[wid] = bal;
        }
        __syncthreads();
        if (tid == 0) {
            int nw = 0; bool found = false;
#pragma unroll
            for (int w2 = 0; w2 < 8; ++w2) {
                if (!found && ibal[w2]) { nw = w2 * 32 + __ffs(ibal[w2]) - 1; found = true; }
            }
            s_new = found ? nw : 0;
            out[t] = (float)s_new;
        }
        __syncthreads();
        prev = s_new;
    }
}

extern "C" void kernel_launch(void* const* d_in, const int* in_sizes, int n_in,
                              void* d_out, int out_size) {
    // Size-verified mapping (dict order of setup_inputs, skipping the scalar c).
    const int want[14] = {640, 512, 16384, 102400, 81920, 81920, 184320,
                          2880, 16384, 256, 65536, 256, 65536, 256};
    const float* ptr[14];
    int j = 0;
    for (int i = 0; i < 14; ++i) {
        while (j < n_in && in_sizes[j] != want[i]) ++j;
        ptr[i] = (j < n_in) ? (const float*)d_in[j] : (const float*)d_in[n_in - 1];
        ++j;
    }
    const float* y       = ptr[0];
    const float* samples = ptr[1];
    const float* emb     = ptr[2];
    const float* condW   = ptr[3];
    const float* wpast   = ptr[4];
    const float* wpres   = ptr[5];
    const float* wo      = ptr[6];
    const float* wob     = ptr[7];
    const float* wol     = ptr[8];
    const float* wobl    = ptr[9];
    const float* e1w     = ptr[10];
    const float* e1b     = ptr[11];
    const float* e2w     = ptr[12];
    const float* e2b     = ptr[13];
    float* out = (float*)d_out;

    k_zero_hist<<<(TT * LL * RR + 1023) / 1024, 1024>>>();
    k_conds<<<(1280 * 8 + 255) / 256, 256>>>(condW, y);
    k_main<<<1, 1024>>>(emb, wpast, wpres, wo, wob, wol, wobl,
                        e1w, e1b, e2w, e2b, samples, out);
}

// round 8
// speedup vs baseline: 3.6350x; 1.5376x over previous
#include <cuda_runtime.h>

// FastWaveNet autoregressive sampler — 8-CTA cluster, SMEM-resident weights.
// Each CTA holds a 1/8 slice of all weights in dynamic SMEM (staged once).
// One cluster barrier per layer (K-split output matvec, partial-sum via L2),
// two in the head. x/skip/softmax replicated bit-identically in every CTA.

#define TT   512
#define LL   10
#define NC   8

__device__ float d_hist[TT * LL * 64];    // [slot][j][r]
__device__ float d_conds[8 * LL * 128];   // [frame][j*128+g]
__device__ float d_part[2][NC * 320];     // layer-parity double buffer
__device__ float d_hidg[256];
__device__ float d_logitsg[256];

__global__ void k_zero_hist() {
    int i = blockIdx.x * blockDim.x + threadIdx.x;
    if (i < TT * LL * 64) d_hist[i] = 0.f;
}

__global__ void k_conds(const float* __restrict__ condW, const float* __restrict__ y) {
    int i = blockIdx.x * blockDim.x + threadIdx.x;
    if (i >= 1280 * 8) return;
    int row = i >> 3, f = i & 7;
    const float* w = condW + row * 80;
    float a = 0.f;
#pragma unroll
    for (int m = 0; m < 80; ++m) a += w[m] * y[m * 8 + f];
    d_conds[f * 1280 + row] = a;
}

__device__ __forceinline__ float dot4(float4 a, float4 b) {
    return a.x * b.x + a.y * b.y + a.z * b.z + a.w * b.w;
}
__device__ __forceinline__ float red16(float v) {
    v += __shfl_xor_sync(~0u, v, 1);
    v += __shfl_xor_sync(~0u, v, 2);
    v += __shfl_xor_sync(~0u, v, 4);
    v += __shfl_xor_sync(~0u, v, 8);
    return v;
}
__device__ __forceinline__ float red32(float v) {
    v += __shfl_xor_sync(~0u, v, 1);
    v += __shfl_xor_sync(~0u, v, 2);
    v += __shfl_xor_sync(~0u, v, 4);
    v += __shfl_xor_sync(~0u, v, 8);
    v += __shfl_xor_sync(~0u, v, 16);
    return v;
}

#define CLUSTER_ARRIVE() asm volatile("barrier.cluster.arrive.aligned;" ::: "memory")
#define CLUSTER_WAIT()   asm volatile("barrier.cluster.wait.aligned;" ::: "memory")

struct SM {
    float wpa[10][16][64];   // phase1 rows owned by this CTA (first 8 = zw, next 8 = zf)
    float wpr[10][16][64];
    float wo[9][8][320];     // [layer][local z col][row]  (K-split slice)
    float wol[8][256];       // [local z col][row]
    float wob[9][320];
    float wobl[256];
    float past[10][64];
    float x[64];
    float h[16];
    float z[8];
    float skip[256];
    float rsm[256];
    float hid[256];
    float buf[256];
    float cs[256];
    float red[32];
    float scn[32];
    float shv[2];
    unsigned ibal[8];
    int snew;
};

__global__ void __launch_bounds__(1024, 1) __cluster_dims__(NC, 1, 1) k_main(
    const float* __restrict__ emb,
    const float* __restrict__ wpast,
    const float* __restrict__ wpres,
    const float* __restrict__ wo,  const float* __restrict__ wob,
    const float* __restrict__ wol, const float* __restrict__ wobl,
    const float* __restrict__ e1w, const float* __restrict__ e1b,
    const float* __restrict__ e2w, const float* __restrict__ e2b,
    const float* __restrict__ samples,
    float* __restrict__ out)
{
    extern __shared__ char smraw[];
    SM* sm = (SM*)smraw;
    const int tid  = threadIdx.x;
    const int lane = tid & 31;
    const int wid  = tid >> 5;
    const int c    = blockIdx.x;

    // ---- stage weight slices into SMEM (once per launch) ----
    for (int idx = tid; idx < 10 * 16 * 64; idx += 1024) {
        int j = idx >> 10, rem = idx & 1023, i = rem >> 6, k = rem & 63;
        int g = (i < 8) ? (c * 8 + i) : (64 + c * 8 + (i - 8));
        sm->wpa[j][i][k] = wpast[(j * 128 + g) * 64 + k];
        sm->wpr[j][i][k] = wpres[(j * 128 + g) * 64 + k];
    }
    for (int r2 = tid; r2 < 9 * 320; r2 += 1024) {
        int j = r2 / 320, row = r2 % 320;
        const float* p = wo + (j * 320 + row) * 64 + c * 8;
#pragma unroll
        for (int k = 0; k < 8; ++k) sm->wo[j][k][row] = p[k];
    }
    for (int row = tid; row < 256; row += 1024) {
        const float* p = wol + row * 64 + c * 8;
#pragma unroll
        for (int k = 0; k < 8; ++k) sm->wol[k][row] = p[k];
    }
    for (int idx = tid; idx < 9 * 320; idx += 1024) ((float*)sm->wob)[idx] = wob[idx];
    for (int idx = tid; idx < 256;     idx += 1024) sm->wobl[idx] = wobl[idx];

    // e1/e2 slices live in registers: warp w owns row c*32+w, lane owns 8 cols
    const int rw = c * 32 + wid;
    const float4 e1r0 = *(const float4*)(e1w + rw * 256 + lane * 8);
    const float4 e1r1 = *(const float4*)(e1w + rw * 256 + lane * 8 + 4);
    const float4 e2r0 = *(const float4*)(e2w + rw * 256 + lane * 8);
    const float4 e2r1 = *(const float4*)(e2w + rw * 256 + lane * 8 + 4);
    const float e1bias = e1b[rw];
    const float e2bias = e2b[rw];
    __syncthreads();

    int prev = 127;
    for (int t = 0; t < TT; ++t) {
        const int frame = t >> 6;

        // --- prologue: past vectors, x0 = emb[prev], skip = 0 ---
        if (tid < 640) {
            int j = tid >> 6, r = tid & 63;
            int slot = (t + 512 - (1 << j)) & 511;
            sm->past[j][r] = d_hist[slot * 640 + j * 64 + r];
        } else if (tid < 704) {
            sm->x[tid - 640] = emb[prev * 64 + (tid - 640)];
        } else if (tid < 960) {
            sm->skip[tid - 704] = 0.f;
        }
        __syncthreads();

#pragma unroll 1
        for (int j = 0; j < LL; ++j) {
            // CTA0 archives layer input x (pre-update) into the history ring
            if (c == 0 && tid >= 256 && tid < 320)
                d_hist[(t & 511) * 640 + j * 64 + (tid - 256)] = sm->x[tid - 256];

            // phase1: this CTA's 16 h-rows (dot length 64, 16 lanes/row)
            if (tid < 256) {
                int i = tid >> 4, l4 = tid & 15;
                float4 wp = *(const float4*)&sm->wpa[j][i][l4 * 4];
                float4 wq = *(const float4*)&sm->wpr[j][i][l4 * 4];
                float4 pp = *(const float4*)&sm->past[j][l4 * 4];
                float4 xx = *(const float4*)&sm->x[l4 * 4];
                float acc = red16(dot4(wp, pp) + dot4(wq, xx));
                if (l4 == 0) {
                    int g = (i < 8) ? (c * 8 + i) : (64 + c * 8 + (i - 8));
                    sm->h[i] = acc + d_conds[frame * 1280 + j * 128 + g];
                }
            }
            __syncthreads();
            if (tid < 8) {
                float zw = sm->h[tid], zf = sm->h[tid + 8];
                sm->z[tid] = tanhf(zw) * (1.f / (1.f + expf(-zf)));
            }
            __syncthreads();

            // phase3 partial: K-split — this CTA's 8 z-cols vs all rows
            const int NR = (j < 9) ? 320 : 256;
            if (tid < NR) {
                float p;
                if (j < 9) {
                    p = sm->wo[j][0][tid] * sm->z[0];
#pragma unroll
                    for (int k = 1; k < 8; ++k) p += sm->wo[j][k][tid] * sm->z[k];
                } else {
                    p = sm->wol[0][tid] * sm->z[0];
#pragma unroll
                    for (int k = 1; k < 8; ++k) p += sm->wol[k][tid] * sm->z[k];
                }
                d_part[j & 1][c * 320 + tid] = p;
            }
            CLUSTER_ARRIVE();
            CLUSTER_WAIT();

            // replicated reduction of the 8 partials (identical in every CTA)
            if (tid < NR) {
                float o = 0.f;
#pragma unroll
                for (int c2 = 0; c2 < NC; ++c2) o += d_part[j & 1][c2 * 320 + tid];
                if (j < 9) {
                    o += sm->wob[j][tid];
                    if (tid < 64) sm->x[tid] += o;
                    else          sm->skip[tid - 64] += o;
                } else {
                    sm->skip[tid] += o + sm->wobl[tid];
                }
            }
            __syncthreads();
        }

        // --- head ---
        if (tid < 256) sm->rsm[tid] = fmaxf(sm->skip[tid], 0.f);
        __syncthreads();
        {
            float4 r0 = *(const float4*)&sm->rsm[lane * 8];
            float4 r1 = *(const float4*)&sm->rsm[lane * 8 + 4];
            float acc = red32(dot4(e1r0, r0) + dot4(e1r1, r1));
            if (lane == 0) d_hidg[rw] = fmaxf(acc + e1bias, 0.f);
        }
        CLUSTER_ARRIVE();
        CLUSTER_WAIT();
        if (tid < 256) sm->hid[tid] = d_hidg[tid];
        __syncthreads();
        {
            float4 r0 = *(const float4*)&sm->hid[lane * 8];
            float4 r1 = *(const float4*)&sm->hid[lane * 8 + 4];
            float acc = red32(dot4(e2r0, r0) + dot4(e2r1, r1));
            if (lane == 0) d_logitsg[rw] = acc + e2bias;
        }
        CLUSTER_ARRIVE();
        CLUSTER_WAIT();
        if (tid < 256) sm->buf[tid] = d_logitsg[tid];
        __syncthreads();

        // --- softmax -> cumsum -> first index with cumsum > s (replicated) ---
        float l = (tid < 256) ? sm->buf[tid] : -1e30f;
        {
            float v = l;
#pragma unroll
            for (int o = 16; o; o >>= 1) v = fmaxf(v, __shfl_xor_sync(~0u, v, o));
            if (lane == 0) sm->red[wid] = v;
        }
        __syncthreads();
        if (tid < 32) {
            float m2 = sm->red[tid];
#pragma unroll
            for (int o = 16; o; o >>= 1) m2 = fmaxf(m2, __shfl_xor_sync(~0u, m2, o));
            if (tid == 0) sm->shv[0] = m2;
        }
        __syncthreads();
        float mx = sm->shv[0];
        float ev = (tid < 256) ? expf(l - mx) : 0.f;
        if (tid < 256) sm->buf[tid] = ev;
        {
            float v = ev;
#pragma unroll
            for (int o = 16; o; o >>= 1) v += __shfl_xor_sync(~0u, v, o);
            if (lane == 0) sm->red[wid] = v;
        }
        __syncthreads();
        if (tid < 32) {
            float s2 = sm->red[tid];
#pragma unroll
            for (int o = 16; o; o >>= 1) s2 += __shfl_xor_sync(~0u, s2, o);
            if (tid == 0) sm->shv[1] = s2;
        }
        __syncthreads();
        float Z = sm->shv[1];
        if (tid < 256) sm->buf[tid] = sm->buf[tid] / Z;
        __syncthreads();
        if (tid < 32) {
            float ssum = 0.f;
#pragma unroll
            for (int k = 0; k < 8; ++k) ssum += sm->buf[tid * 8 + k];
#pragma unroll
            for (int d = 1; d < 32; d <<= 1) {
                float u = __shfl_up_sync(~0u, ssum, d);
                if (lane >= d) ssum += u;
            }
            sm->scn[tid] = ssum;
        }
        __syncthreads();
        if (tid < 256) {
            int b = tid >> 3;
            float c0 = b ? sm->scn[b - 1] : 0.f;
            for (int k = b * 8; k <= tid; ++k) c0 += sm->buf[k];
            sm->cs[tid] = c0;
        }
        __syncthreads();
        {
            float sv = samples[t];
            bool pred = (tid < 256) && (sm->cs[tid] > sv);
            unsigned bal = __ballot_sync(~0u, pred);
            if (lane == 0 && wid < 8) sm->ibal[wid] = bal;
        }
        __syncthreads();
        if (tid == 0) {
            int nw = 0; bool found = false;
#pragma unroll
            for (int w2 = 0; w2 < 8; ++w2) {
                if (!found && sm->ibal[w2]) { nw = w2 * 32 + __ffs(sm->ibal[w2]) - 1; found = true; }
            }
            sm->snew = found ? nw : 0;
            if (c == 0) out[t] = (float)sm->snew;
        }
        __syncthreads();
        prev = sm->snew;
    }
}

extern "C" void kernel_launch(void* const* d_in, const int* in_sizes, int n_in,
                              void* d_out, int out_size) {
    const int want[14] = {640, 512, 16384, 102400, 81920, 81920, 184320,
                          2880, 16384, 256, 65536, 256, 65536, 256};
    const float* ptr[14];
    int j = 0;
    for (int i = 0; i < 14; ++i) {
        while (j < n_in && in_sizes[j] != want[i]) ++j;
        ptr[i] = (j < n_in) ? (const float*)d_in[j] : (const float*)d_in[n_in - 1];
        ++j;
    }
    const float* y       = ptr[0];
    const float* samples = ptr[1];
    const float* emb     = ptr[2];
    const float* condW   = ptr[3];
    const float* wpast   = ptr[4];
    const float* wpres   = ptr[5];
    const float* wo      = ptr[6];
    const float* wob     = ptr[7];
    const float* wol     = ptr[8];
    const float* wobl    = ptr[9];
    const float* e1w     = ptr[10];
    const float* e1b     = ptr[11];
    const float* e2w     = ptr[12];
    const float* e2b     = ptr[13];
    float* out = (float*)d_out;

    static_assert(sizeof(SM) < 230000, "smem too big");
    cudaFuncSetAttribute(k_main, cudaFuncAttributeMaxDynamicSharedMemorySize,
                         (int)sizeof(SM));

    k_zero_hist<<<(TT * LL * 64 + 1023) / 1024, 1024>>>();
    k_conds<<<(1280 * 8 + 255) / 256, 256>>>(condW, y);
    k_main<<<NC, 1024, sizeof(SM)>>>(emb, wpast, wpres, wo, wob, wol, wobl,
                                     e1w, e1b, e2w, e2b, samples, out);
}